// round 2
// baseline (speedup 1.0000x reference)
#include <cuda_runtime.h>
#include <cstdint>

#define HID 128
#define OUTD 100
#define NSTEPS 64
#define NP1 (NSTEPS + 1)
#define B2 4096
#define SPB 8                      // samples per block (one per warp)
#define THREADS 256
#define STEP_TILES 4
#define STEPS_PER_TILE (NSTEPS / STEP_TILES)
#define NSB (B2 / SPB)             // 512 sample-groups

// Deterministic partial sums: [step_tile][sample]
__device__ float g_partial[STEP_TILES * B2];

__device__ __forceinline__ float tanh_fast(float x) {
    float e = __expf(2.0f * x);
    return 1.0f - __fdividef(2.0f, e + 1.0f);
}

__device__ __forceinline__ uint32_t smem_u32(const void* p) {
    return (uint32_t)__cvta_generic_to_shared(p);
}

__device__ __forceinline__ unsigned long long pack2(float lo, float hi) {
    unsigned long long r;
    asm("mov.b64 %0,{%1,%2};" : "=l"(r) : "f"(lo), "f"(hi));
    return r;
}

__device__ __forceinline__ void unpack2(unsigned long long v, float& lo, float& hi) {
    asm("mov.b64 {%0,%1},%2;" : "=f"(lo), "=f"(hi) : "l"(v));
}

// One fused layer pass: (z,zp,zpp)[4] += sum_k hh[k] * W[k, c0..c0+3]
// using packed fp32x2 FMAs. a_h points at duplicated activations
// [h,h,h',h',h'',h'',pad,pad] (32B stride), a_w at W row base + lane col offset.
__device__ __forceinline__ void gemv3_f32x2(
    uint32_t a_h, uint32_t a_w,
    unsigned long long& z01, unsigned long long& z23,
    unsigned long long& zp01, unsigned long long& zp23,
    unsigned long long& zpp01, unsigned long long& zpp23)
{
#pragma unroll 8
    for (int k = 0; k < HID; k++) {
        unsigned long long hv2, hd2, hdd2, w01, w23;
        asm volatile("ld.shared.v2.u64 {%0,%1},[%2];"
                     : "=l"(hv2), "=l"(hd2) : "r"(a_h));
        asm volatile("ld.shared.u64 %0,[%1];"
                     : "=l"(hdd2) : "r"(a_h + 16));
        asm volatile("ld.shared.v2.u64 {%0,%1},[%2];"
                     : "=l"(w01), "=l"(w23) : "r"(a_w));
        asm("fma.rn.f32x2 %0,%1,%2,%0;" : "+l"(z01)   : "l"(hv2),  "l"(w01));
        asm("fma.rn.f32x2 %0,%1,%2,%0;" : "+l"(z23)   : "l"(hv2),  "l"(w23));
        asm("fma.rn.f32x2 %0,%1,%2,%0;" : "+l"(zp01)  : "l"(hd2),  "l"(w01));
        asm("fma.rn.f32x2 %0,%1,%2,%0;" : "+l"(zp23)  : "l"(hd2),  "l"(w23));
        asm("fma.rn.f32x2 %0,%1,%2,%0;" : "+l"(zpp01) : "l"(hdd2), "l"(w01));
        asm("fma.rn.f32x2 %0,%1,%2,%0;" : "+l"(zpp23) : "l"(hdd2), "l"(w23));
        a_h += 32;
        a_w += HID * 4;
    }
}

__global__ __launch_bounds__(THREADS, 1)
void bsde_main(const float* __restrict__ W1, const float* __restrict__ b1,
               const float* __restrict__ W2, const float* __restrict__ b2,
               const float* __restrict__ W3, const float* __restrict__ b3,
               const float* __restrict__ W4, const float* __restrict__ b4,
               const int*   __restrict__ sn, const float* __restrict__ ss,
               const float* __restrict__ sdB, const float* __restrict__ tptr)
{
    extern __shared__ float smem[];
    float* sW2  = smem;                    // 128*128
    float* sW3  = sW2 + HID * HID;         // 128*128
    float* sW4T = sW3 + HID * HID;         // 100*128 (transposed: [n][k])
    float* sw1s = sW4T + OUTD * HID;       // 128
    float* sw1t = sw1s + HID;              // 128
    float* sb1  = sw1t + HID;              // 128
    float* sb2  = sb1 + HID;               // 128
    float* sb3  = sb2 + HID;               // 128
    float* sb4  = sb3 + HID;               // 128 (100 used)
    float* sh   = sb4 + HID;               // SPB * HID * 8 duplicated activations

    const int tid = threadIdx.x;

    for (int i = tid; i < HID * HID; i += THREADS) { sW2[i] = W2[i]; sW3[i] = W3[i]; }
    for (int i = tid; i < OUTD * HID; i += THREADS) {
        int n = i >> 7;
        int k = i & (HID - 1);
        sW4T[i] = W4[k * OUTD + n];
    }
    if (tid < HID) {
        sw1s[tid] = W1[tid];
        sw1t[tid] = W1[HID + tid];
        sb1[tid]  = b1[tid];
        sb2[tid]  = b2[tid];
        sb3[tid]  = b3[tid];
        sb4[tid]  = (tid < OUTD) ? b4[tid] : 0.0f;
    }
    __syncthreads();

    const int st   = blockIdx.x % STEP_TILES;
    const int sg   = blockIdx.x / STEP_TILES;
    const int w    = tid >> 5;
    const int lane = tid & 31;
    const int b    = sg * SPB + w;
    float* shw = sh + w * (HID * 8);
    const int c0 = lane * 4;

    const uint32_t a_h_base  = smem_u32(shw);
    const uint32_t a_w2_base = smem_u32(&sW2[c0]);
    const uint32_t a_w3_base = smem_u32(&sW3[c0]);

    const float t      = *tptr;
    const float dt     = t / (float)NSTEPS;
    const float halfdt = 0.5f * dt;

    float w1sr[4], w1tr[4], b1r[4];
    unsigned long long b2p01, b2p23, b3p01, b3p23;
#pragma unroll
    for (int m = 0; m < 4; m++) {
        w1sr[m] = sw1s[c0 + m];
        w1tr[m] = sw1t[c0 + m];
        b1r[m]  = sb1[c0 + m];
    }
    b2p01 = pack2(sb2[c0], sb2[c0 + 1]);
    b2p23 = pack2(sb2[c0 + 2], sb2[c0 + 3]);
    b3p01 = pack2(sb3[c0], sb3[c0 + 1]);
    b3p23 = pack2(sb3[c0 + 2], sb3[c0 + 3]);

    const int j0 = st * STEPS_PER_TILE;
    float acc = 0.0f;

    float s_nxt  = ss[b * NP1 + (NSTEPS - j0)];
    int   n_nxt  = sn[b * NP1 + (NSTEPS - j0)];
    float dB_nxt = sdB[b * NSTEPS + (NSTEPS - 1 - j0)];

    for (int jj = 0; jj < STEPS_PER_TILE; ++jj) {
        const int j = j0 + jj;
        const float s  = s_nxt;
        const int   n  = n_nxt;
        const float dB = dB_nxt;
        if (jj + 1 < STEPS_PER_TILE) {
            s_nxt  = ss[b * NP1 + (NSTEPS - (j + 1))];
            n_nxt  = sn[b * NP1 + (NSTEPS - (j + 1))];
            dB_nxt = sdB[b * NSTEPS + (NSTEPS - 1 - (j + 1))];
        }
        // scan semantics: j=0 evaluated at tk=t, j>=1 at t - dt*(j-1)
        const float tk = (j == 0) ? t : (t - dt * (float)(j - 1));

        // ---- layer 1 (analytic forward-mode in s), stored duplicated ----
#pragma unroll
        for (int m = 0; m < 4; m++) {
            float z = fmaf(s, w1sr[m], fmaf(tk, w1tr[m], b1r[m]));
            float h = tanh_fast(z);
            float g = 1.0f - h * h;
            float hd  = g * w1sr[m];
            float hdd = -2.0f * h * hd * w1sr[m];
            *(float4*)&shw[(c0 + m) * 8]     = make_float4(h, h, hd, hd);
            *(float4*)&shw[(c0 + m) * 8 + 4] = make_float4(hdd, hdd, 0.0f, 0.0f);
        }
        __syncwarp();

        // ---- layer 2 ----
        unsigned long long z01 = b2p01, z23 = b2p23;
        unsigned long long zp01 = 0, zp23 = 0, zpp01 = 0, zpp23 = 0;
        gemv3_f32x2(a_h_base, a_w2_base, z01, z23, zp01, zp23, zpp01, zpp23);
        __syncwarp();

        float zv[4], zpv[4], zppv[4];
        unpack2(z01, zv[0], zv[1]);   unpack2(z23, zv[2], zv[3]);
        unpack2(zp01, zpv[0], zpv[1]); unpack2(zp23, zpv[2], zpv[3]);
        unpack2(zpp01, zppv[0], zppv[1]); unpack2(zpp23, zppv[2], zppv[3]);
#pragma unroll
        for (int m = 0; m < 4; m++) {
            float h = tanh_fast(zv[m]);
            float g = 1.0f - h * h;
            float hd  = g * zpv[m];
            float hdd = fmaf(g, zppv[m], -2.0f * h * hd * zpv[m]);
            *(float4*)&shw[(c0 + m) * 8]     = make_float4(h, h, hd, hd);
            *(float4*)&shw[(c0 + m) * 8 + 4] = make_float4(hdd, hdd, 0.0f, 0.0f);
        }
        __syncwarp();

        // ---- layer 3 ----
        z01 = b3p01; z23 = b3p23;
        zp01 = 0; zp23 = 0; zpp01 = 0; zpp23 = 0;
        gemv3_f32x2(a_h_base, a_w3_base, z01, z23, zp01, zp23, zpp01, zpp23);

        float hv[4], hd[4], hdd[4];
        unpack2(z01, zv[0], zv[1]);   unpack2(z23, zv[2], zv[3]);
        unpack2(zp01, zpv[0], zpv[1]); unpack2(zp23, zpv[2], zpv[3]);
        unpack2(zpp01, zppv[0], zppv[1]); unpack2(zpp23, zppv[2], zppv[3]);
#pragma unroll
        for (int m = 0; m < 4; m++) {
            float h = tanh_fast(zv[m]);
            float g = 1.0f - h * h;
            hv[m]  = h;
            hd[m]  = g * zpv[m];
            hdd[m] = fmaf(g, zppv[m], -2.0f * h * hd[m] * zpv[m]);
        }

        // ---- layer 4: dot with column n of W4 ----
        float4 wv4 = *(const float4*)&sW4T[n * HID + c0];
        float pu  = hv[0] * wv4.x + hv[1] * wv4.y + hv[2] * wv4.z + hv[3] * wv4.w;
        float pp  = hd[0] * wv4.x + hd[1] * wv4.y + hd[2] * wv4.z + hd[3] * wv4.w;
        float ppp = hdd[0] * wv4.x + hdd[1] * wv4.y + hdd[2] * wv4.z + hdd[3] * wv4.w;
#pragma unroll
        for (int off = 16; off >= 1; off >>= 1) {
            pu  += __shfl_xor_sync(0xffffffffu, pu,  off);
            pp  += __shfl_xor_sync(0xffffffffu, pp,  off);
            ppp += __shfl_xor_sync(0xffffffffu, ppp, off);
        }

        float contrib = -fmaf(pp, dB, ppp * halfdt);   // -(ps*dB + pss*dt/2)
        if (j == 0) contrib += pu + sb4[n];            // terminal value term
        acc += contrib;
    }

    if (lane == 0) g_partial[st * B2 + b] = acc;
}

__global__ void bsde_final(const float* __restrict__ ss, float* __restrict__ out)
{
    int b = blockIdx.x * blockDim.x + threadIdx.x;
    if (b >= B2) return;
    float u = 0.0f;
#pragma unroll
    for (int st = 0; st < STEP_TILES; st++) u += g_partial[st * B2 + b];
    out[b] = u;
    float s0 = ss[b * NP1];
    out[B2 + b] = 3.9894228040143274f * expf(-500000.0f * (s0 * s0));
}

extern "C" void kernel_launch(void* const* d_in, const int* in_sizes, int n_in,
                              void* d_out, int out_size)
{
    const float* W1   = (const float*)d_in[0];
    const float* b1   = (const float*)d_in[1];
    const float* W2   = (const float*)d_in[2];
    const float* b2   = (const float*)d_in[3];
    const float* W3   = (const float*)d_in[4];
    const float* b3   = (const float*)d_in[5];
    const float* W4   = (const float*)d_in[6];
    const float* b4   = (const float*)d_in[7];
    const int*   sn   = (const int*)d_in[8];
    const float* ss   = (const float*)d_in[9];
    const float* sdB  = (const float*)d_in[10];
    const float* tptr = (const float*)d_in[11];
    float* out = (float*)d_out;

    size_t smem_bytes = (size_t)(2 * HID * HID + OUTD * HID + 6 * HID + SPB * HID * 8) * sizeof(float);
    cudaFuncSetAttribute(bsde_main, cudaFuncAttributeMaxDynamicSharedMemorySize, (int)smem_bytes);

    bsde_main<<<NSB * STEP_TILES, THREADS, smem_bytes>>>(W1, b1, W2, b2, W3, b3, W4, b4,
                                                         sn, ss, sdB, tptr);
    bsde_final<<<(B2 + 255) / 256, 256>>>(ss, out);
}

// round 3
// speedup vs baseline: 1.3426x; 1.3426x over previous
#include <cuda_runtime.h>

#define HID 128
#define OUTD 100
#define NSTEPS 64
#define NP1 (NSTEPS + 1)
#define B2 4096
#define SPB 16                     // samples per block (one per warp)
#define THREADS 512
#define STEP_TILES 4
#define STEPS_PER_TILE (NSTEPS / STEP_TILES)
#define NSB (B2 / SPB)             // 256 sample-groups

// Deterministic partial sums: [step_tile][sample]
__device__ float g_partial[STEP_TILES * B2];

__device__ __forceinline__ float tanh_fast(float x) {
    // accurate tanh via exp-based form; ~1e-6 rel err, saturates correctly
    float e = __expf(2.0f * x);
    return 1.0f - __fdividef(2.0f, e + 1.0f);
}

__global__ __launch_bounds__(THREADS, 1)
void bsde_main(const float* __restrict__ W1, const float* __restrict__ b1,
               const float* __restrict__ W2, const float* __restrict__ b2,
               const float* __restrict__ W3, const float* __restrict__ b3,
               const float* __restrict__ W4, const float* __restrict__ b4,
               const int*   __restrict__ sn, const float* __restrict__ ss,
               const float* __restrict__ sdB, const float* __restrict__ tptr)
{
    extern __shared__ float smem[];
    float* sW2  = smem;                    // 128*128
    float* sW3  = sW2 + HID * HID;         // 128*128
    float* sW4T = sW3 + HID * HID;         // 100*128 (transposed: [n][k])
    float* sw1s = sW4T + OUTD * HID;       // 128
    float* sw1t = sw1s + HID;              // 128
    float* sb1  = sw1t + HID;              // 128
    float* sb2  = sb1 + HID;               // 128
    float* sb3  = sb2 + HID;               // 128
    float* sb4  = sb3 + HID;               // 128 (100 used)
    float* sh   = sb4 + HID;               // SPB * HID * 4 (h,h',h'',pad)

    const int tid = threadIdx.x;

    for (int i = tid; i < HID * HID; i += THREADS) { sW2[i] = W2[i]; sW3[i] = W3[i]; }
    for (int i = tid; i < OUTD * HID; i += THREADS) {
        int n = i >> 7;            // / HID
        int k = i & (HID - 1);
        sW4T[i] = W4[k * OUTD + n];
    }
    if (tid < HID) {
        sw1s[tid] = W1[tid];
        sw1t[tid] = W1[HID + tid];
        sb1[tid]  = b1[tid];
        sb2[tid]  = b2[tid];
        sb3[tid]  = b3[tid];
        sb4[tid]  = (tid < OUTD) ? b4[tid] : 0.0f;
    }
    __syncthreads();

    const int st   = blockIdx.x % STEP_TILES;
    const int sg   = blockIdx.x / STEP_TILES;
    const int w    = tid >> 5;
    const int lane = tid & 31;
    const int b    = sg * SPB + w;
    float* shw = sh + w * (HID * 4);
    const int c0 = lane * 4;

    const float t      = *tptr;
    const float dt     = t / (float)NSTEPS;
    const float halfdt = 0.5f * dt;

    // per-lane layer-1 constants for this lane's 4 hidden columns
    float w1sr[4], w1tr[4], b1r[4], b2r[4], b3r[4];
#pragma unroll
    for (int m = 0; m < 4; m++) {
        w1sr[m] = sw1s[c0 + m];
        w1tr[m] = sw1t[c0 + m];
        b1r[m]  = sb1[c0 + m];
        b2r[m]  = sb2[c0 + m];
        b3r[m]  = sb3[c0 + m];
    }

    const int j0 = st * STEPS_PER_TILE;
    float acc = 0.0f;

    // prefetch step inputs (broadcast loads, overlapped with compute)
    float s_nxt  = ss[b * NP1 + (NSTEPS - j0)];
    int   n_nxt  = sn[b * NP1 + (NSTEPS - j0)];
    float dB_nxt = sdB[b * NSTEPS + (NSTEPS - 1 - j0)];

    for (int jj = 0; jj < STEPS_PER_TILE; ++jj) {
        const int j = j0 + jj;
        const float s  = s_nxt;
        const int   n  = n_nxt;
        const float dB = dB_nxt;
        if (jj + 1 < STEPS_PER_TILE) {
            s_nxt  = ss[b * NP1 + (NSTEPS - (j + 1))];
            n_nxt  = sn[b * NP1 + (NSTEPS - (j + 1))];
            dB_nxt = sdB[b * NSTEPS + (NSTEPS - 1 - (j + 1))];
        }
        // scan carry semantics: j=0 evaluated at tk=t, j>=1 at t - dt*(j-1)
        const float tk = (j == 0) ? t : (t - dt * (float)(j - 1));

        // ---- layer 1 (analytic forward-mode in s) ----
        float hv[4], hd[4], hdd[4];
#pragma unroll
        for (int m = 0; m < 4; m++) {
            float z = fmaf(s, w1sr[m], fmaf(tk, w1tr[m], b1r[m]));
            float h = tanh_fast(z);
            float g = 1.0f - h * h;
            hv[m]  = h;
            hd[m]  = g * w1sr[m];
            hdd[m] = -2.0f * h * hd[m] * w1sr[m];
        }
        __syncwarp();
#pragma unroll
        for (int m = 0; m < 4; m++)
            *(float4*)&shw[(c0 + m) * 4] = make_float4(hv[m], hd[m], hdd[m], 0.0f);
        __syncwarp();

        // ---- layer 2: z = h@W2, zp = h'@W2, zpp = h''@W2 ----
        float z[4], zp[4], zpp[4];
#pragma unroll
        for (int m = 0; m < 4; m++) { z[m] = b2r[m]; zp[m] = 0.0f; zpp[m] = 0.0f; }
#pragma unroll 8
        for (int k = 0; k < HID; k++) {
            float4 hh = *(const float4*)&shw[k * 4];          // broadcast
            float4 wv = *(const float4*)&sW2[k * HID + c0];   // conflict-free
            z[0] = fmaf(hh.x, wv.x, z[0]); zp[0] = fmaf(hh.y, wv.x, zp[0]); zpp[0] = fmaf(hh.z, wv.x, zpp[0]);
            z[1] = fmaf(hh.x, wv.y, z[1]); zp[1] = fmaf(hh.y, wv.y, zp[1]); zpp[1] = fmaf(hh.z, wv.y, zpp[1]);
            z[2] = fmaf(hh.x, wv.z, z[2]); zp[2] = fmaf(hh.y, wv.z, zp[2]); zpp[2] = fmaf(hh.z, wv.z, zpp[2]);
            z[3] = fmaf(hh.x, wv.w, z[3]); zp[3] = fmaf(hh.y, wv.w, zp[3]); zpp[3] = fmaf(hh.z, wv.w, zpp[3]);
        }
        __syncwarp();
#pragma unroll
        for (int m = 0; m < 4; m++) {
            float h = tanh_fast(z[m]);
            float g = 1.0f - h * h;
            hv[m]  = h;
            hd[m]  = g * zp[m];
            hdd[m] = fmaf(g, zpp[m], -2.0f * h * hd[m] * zp[m]);
            *(float4*)&shw[(c0 + m) * 4] = make_float4(hv[m], hd[m], hdd[m], 0.0f);
        }
        __syncwarp();

        // ---- layer 3 ----
#pragma unroll
        for (int m = 0; m < 4; m++) { z[m] = b3r[m]; zp[m] = 0.0f; zpp[m] = 0.0f; }
#pragma unroll 8
        for (int k = 0; k < HID; k++) {
            float4 hh = *(const float4*)&shw[k * 4];
            float4 wv = *(const float4*)&sW3[k * HID + c0];
            z[0] = fmaf(hh.x, wv.x, z[0]); zp[0] = fmaf(hh.y, wv.x, zp[0]); zpp[0] = fmaf(hh.z, wv.x, zpp[0]);
            z[1] = fmaf(hh.x, wv.y, z[1]); zp[1] = fmaf(hh.y, wv.y, zp[1]); zpp[1] = fmaf(hh.z, wv.y, zpp[1]);
            z[2] = fmaf(hh.x, wv.z, z[2]); zp[2] = fmaf(hh.y, wv.z, zp[2]); zpp[2] = fmaf(hh.z, wv.z, zpp[2]);
            z[3] = fmaf(hh.x, wv.w, z[3]); zp[3] = fmaf(hh.y, wv.w, zp[3]); zpp[3] = fmaf(hh.z, wv.w, zpp[3]);
        }
#pragma unroll
        for (int m = 0; m < 4; m++) {
            float h = tanh_fast(z[m]);
            float g = 1.0f - h * h;
            hv[m]  = h;
            hd[m]  = g * zp[m];
            hdd[m] = fmaf(g, zpp[m], -2.0f * h * hd[m] * zp[m]);
        }

        // ---- layer 4: dot with column n of W4 (registers) ----
        float4 wv4 = *(const float4*)&sW4T[n * HID + c0];
        float pu  = hv[0] * wv4.x + hv[1] * wv4.y + hv[2] * wv4.z + hv[3] * wv4.w;
        float pp  = hd[0] * wv4.x + hd[1] * wv4.y + hd[2] * wv4.z + hd[3] * wv4.w;
        float ppp = hdd[0] * wv4.x + hdd[1] * wv4.y + hdd[2] * wv4.z + hdd[3] * wv4.w;
#pragma unroll
        for (int off = 16; off >= 1; off >>= 1) {
            pu  += __shfl_xor_sync(0xffffffffu, pu,  off);
            pp  += __shfl_xor_sync(0xffffffffu, pp,  off);
            ppp += __shfl_xor_sync(0xffffffffu, ppp, off);
        }

        float contrib = -fmaf(pp, dB, ppp * halfdt);   // -(ps*dB + pss*dt/2)
        if (j == 0) contrib += pu + sb4[n];            // terminal value term
        acc += contrib;
    }

    if (lane == 0) g_partial[st * B2 + b] = acc;
}

__global__ void bsde_final(const float* __restrict__ ss, float* __restrict__ out)
{
    int b = blockIdx.x * blockDim.x + threadIdx.x;
    if (b >= B2) return;
    float u = 0.0f;
#pragma unroll
    for (int st = 0; st < STEP_TILES; st++) u += g_partial[st * B2 + b];
    out[b] = u;
    // u0 = sqrt(beta/(2pi)) * exp(-beta*s0^2/2) / out_dim,  beta = 1e6
    float s0 = ss[b * NP1];
    out[B2 + b] = 3.9894228040143274f * expf(-500000.0f * (s0 * s0));
}

extern "C" void kernel_launch(void* const* d_in, const int* in_sizes, int n_in,
                              void* d_out, int out_size)
{
    const float* W1   = (const float*)d_in[0];
    const float* b1   = (const float*)d_in[1];
    const float* W2   = (const float*)d_in[2];
    const float* b2   = (const float*)d_in[3];
    const float* W3   = (const float*)d_in[4];
    const float* b3   = (const float*)d_in[5];
    const float* W4   = (const float*)d_in[6];
    const float* b4   = (const float*)d_in[7];
    const int*   sn   = (const int*)d_in[8];
    const float* ss   = (const float*)d_in[9];
    const float* sdB  = (const float*)d_in[10];
    const float* tptr = (const float*)d_in[11];
    float* out = (float*)d_out;

    size_t smem_bytes = (size_t)(2 * HID * HID + OUTD * HID + 6 * HID + SPB * HID * 4) * sizeof(float);
    cudaFuncSetAttribute(bsde_main, cudaFuncAttributeMaxDynamicSharedMemorySize, (int)smem_bytes);

    bsde_main<<<NSB * STEP_TILES, THREADS, smem_bytes>>>(W1, b1, W2, b2, W3, b3, W4, b4,
                                                         sn, ss, sdB, tptr);
    bsde_final<<<(B2 + 255) / 256, 256>>>(ss, out);
}

// round 4
// speedup vs baseline: 1.4182x; 1.0563x over previous
#include <cuda_runtime.h>

#define HID 128
#define OUTD 100
#define NSTEPS 64
#define NP1 (NSTEPS + 1)
#define B2 4096
#define SPB 16                     // samples per block (one per warp)
#define THREADS 512
#define STEP_TILES 4
#define STEPS_PER_TILE (NSTEPS / STEP_TILES)
#define NSB (B2 / SPB)             // 256 sample-groups

// Deterministic partial sums: [step_tile][sample]
__device__ float g_partial[STEP_TILES * B2];

__device__ __forceinline__ float tanh_fast(float x) {
    // accurate tanh via exp-based form; ~1e-6 rel err, saturates correctly
    float e = __expf(2.0f * x);
    return 1.0f - __fdividef(2.0f, e + 1.0f);
}

__global__ __launch_bounds__(THREADS, 1)
void bsde_main(const float* __restrict__ W1, const float* __restrict__ b1,
               const float* __restrict__ W2, const float* __restrict__ b2,
               const float* __restrict__ W3, const float* __restrict__ b3,
               const float* __restrict__ W4, const float* __restrict__ b4,
               const int*   __restrict__ sn, const float* __restrict__ ss,
               const float* __restrict__ sdB, const float* __restrict__ tptr)
{
    extern __shared__ float smem[];
    float* sW2  = smem;                    // 128*128
    float* sW3  = sW2 + HID * HID;         // 128*128
    float* sW4T = sW3 + HID * HID;         // 100*128 (transposed: [n][k])
    float* sw1s = sW4T + OUTD * HID;       // 128
    float* sw1t = sw1s + HID;              // 128
    float* sb1  = sw1t + HID;              // 128
    float* sb2  = sb1 + HID;               // 128
    float* sb3  = sb2 + HID;               // 128
    float* sb4  = sb3 + HID;               // 128 (100 used)
    float* sh   = sb4 + HID;               // SPB * HID * 4 (h,h',h'',pad)

    const int tid = threadIdx.x;

    for (int i = tid; i < HID * HID; i += THREADS) { sW2[i] = W2[i]; sW3[i] = W3[i]; }
    for (int i = tid; i < OUTD * HID; i += THREADS) {
        int n = i >> 7;            // / HID
        int k = i & (HID - 1);
        sW4T[i] = W4[k * OUTD + n];
    }
    if (tid < HID) {
        sw1s[tid] = W1[tid];
        sw1t[tid] = W1[HID + tid];
        sb1[tid]  = b1[tid];
        sb2[tid]  = b2[tid];
        sb3[tid]  = b3[tid];
        sb4[tid]  = (tid < OUTD) ? b4[tid] : 0.0f;
    }
    __syncthreads();

    const int st   = blockIdx.x % STEP_TILES;
    const int sg   = blockIdx.x / STEP_TILES;
    const int w    = tid >> 5;
    const int lane = tid & 31;
    const int b    = sg * SPB + w;
    float* shw = sh + w * (HID * 4);
    const int c0 = lane * 4;

    const float t      = *tptr;
    const float dt     = t / (float)NSTEPS;
    const float halfdt = 0.5f * dt;

    // per-lane layer-1 constants for this lane's 4 hidden columns
    float w1sr[4], w1tr[4], b1r[4], b2r[4], b3r[4];
#pragma unroll
    for (int m = 0; m < 4; m++) {
        w1sr[m] = sw1s[c0 + m];
        w1tr[m] = sw1t[c0 + m];
        b1r[m]  = sb1[c0 + m];
        b2r[m]  = sb2[c0 + m];
        b3r[m]  = sb3[c0 + m];
    }

    const int j0 = st * STEPS_PER_TILE;
    float acc = 0.0f;

    // prefetch step inputs (broadcast loads, overlapped with compute)
    float s_nxt  = ss[b * NP1 + (NSTEPS - j0)];
    int   n_nxt  = sn[b * NP1 + (NSTEPS - j0)];
    float dB_nxt = sdB[b * NSTEPS + (NSTEPS - 1 - j0)];

    for (int jj = 0; jj < STEPS_PER_TILE; ++jj) {
        const int j = j0 + jj;
        const float s  = s_nxt;
        const int   n  = n_nxt;
        const float dB = dB_nxt;
        if (jj + 1 < STEPS_PER_TILE) {
            s_nxt  = ss[b * NP1 + (NSTEPS - (j + 1))];
            n_nxt  = sn[b * NP1 + (NSTEPS - (j + 1))];
            dB_nxt = sdB[b * NSTEPS + (NSTEPS - 1 - (j + 1))];
        }
        // scan carry semantics: j=0 evaluated at tk=t, j>=1 at t - dt*(j-1)
        const float tk = (j == 0) ? t : (t - dt * (float)(j - 1));

        // ---- layer 1 (analytic forward-mode in s) ----
        float hv[4], hd[4], hdd[4];
#pragma unroll
        for (int m = 0; m < 4; m++) {
            float z = fmaf(s, w1sr[m], fmaf(tk, w1tr[m], b1r[m]));
            float h = tanh_fast(z);
            float g = 1.0f - h * h;
            hv[m]  = h;
            hd[m]  = g * w1sr[m];
            hdd[m] = -2.0f * h * hd[m] * w1sr[m];
        }
        __syncwarp();
#pragma unroll
        for (int m = 0; m < 4; m++)
            *(float4*)&shw[(c0 + m) * 4] = make_float4(hv[m], hd[m], hdd[m], 0.0f);
        __syncwarp();

        // ---- layer 2: z = h@W2, zp = h'@W2, zpp = h''@W2 ----
        float z[4], zp[4], zpp[4];
#pragma unroll
        for (int m = 0; m < 4; m++) { z[m] = b2r[m]; zp[m] = 0.0f; zpp[m] = 0.0f; }
#pragma unroll 8
        for (int k = 0; k < HID; k++) {
            float4 hh = *(const float4*)&shw[k * 4];          // broadcast
            float4 wv = *(const float4*)&sW2[k * HID + c0];   // conflict-free
            z[0] = fmaf(hh.x, wv.x, z[0]); zp[0] = fmaf(hh.y, wv.x, zp[0]); zpp[0] = fmaf(hh.z, wv.x, zpp[0]);
            z[1] = fmaf(hh.x, wv.y, z[1]); zp[1] = fmaf(hh.y, wv.y, zp[1]); zpp[1] = fmaf(hh.z, wv.y, zpp[1]);
            z[2] = fmaf(hh.x, wv.z, z[2]); zp[2] = fmaf(hh.y, wv.z, zp[2]); zpp[2] = fmaf(hh.z, wv.z, zpp[2]);
            z[3] = fmaf(hh.x, wv.w, z[3]); zp[3] = fmaf(hh.y, wv.w, zp[3]); zpp[3] = fmaf(hh.z, wv.w, zpp[3]);
        }
        __syncwarp();
#pragma unroll
        for (int m = 0; m < 4; m++) {
            float h = tanh_fast(z[m]);
            float g = 1.0f - h * h;
            hv[m]  = h;
            hd[m]  = g * zp[m];
            hdd[m] = fmaf(g, zpp[m], -2.0f * h * hd[m] * zp[m]);
            *(float4*)&shw[(c0 + m) * 4] = make_float4(hv[m], hd[m], hdd[m], 0.0f);
        }
        __syncwarp();

        // ---- layer 3 ----
#pragma unroll
        for (int m = 0; m < 4; m++) { z[m] = b3r[m]; zp[m] = 0.0f; zpp[m] = 0.0f; }
#pragma unroll 8
        for (int k = 0; k < HID; k++) {
            float4 hh = *(const float4*)&shw[k * 4];
            float4 wv = *(const float4*)&sW3[k * HID + c0];
            z[0] = fmaf(hh.x, wv.x, z[0]); zp[0] = fmaf(hh.y, wv.x, zp[0]); zpp[0] = fmaf(hh.z, wv.x, zpp[0]);
            z[1] = fmaf(hh.x, wv.y, z[1]); zp[1] = fmaf(hh.y, wv.y, zp[1]); zpp[1] = fmaf(hh.z, wv.y, zpp[1]);
            z[2] = fmaf(hh.x, wv.z, z[2]); zp[2] = fmaf(hh.y, wv.z, zp[2]); zpp[2] = fmaf(hh.z, wv.z, zpp[2]);
            z[3] = fmaf(hh.x, wv.w, z[3]); zp[3] = fmaf(hh.y, wv.w, zp[3]); zpp[3] = fmaf(hh.z, wv.w, zpp[3]);
        }
#pragma unroll
        for (int m = 0; m < 4; m++) {
            float h = tanh_fast(z[m]);
            float g = 1.0f - h * h;
            hv[m]  = h;
            hd[m]  = g * zp[m];
            hdd[m] = fmaf(g, zpp[m], -2.0f * h * hd[m] * zp[m]);
        }

        // ---- layer 4: dot with column n of W4 (registers) ----
        float4 wv4 = *(const float4*)&sW4T[n * HID + c0];
        float pu  = hv[0] * wv4.x + hv[1] * wv4.y + hv[2] * wv4.z + hv[3] * wv4.w;
        float pp  = hd[0] * wv4.x + hd[1] * wv4.y + hd[2] * wv4.z + hd[3] * wv4.w;
        float ppp = hdd[0] * wv4.x + hdd[1] * wv4.y + hdd[2] * wv4.z + hdd[3] * wv4.w;
#pragma unroll
        for (int off = 16; off >= 1; off >>= 1) {
            pu  += __shfl_xor_sync(0xffffffffu, pu,  off);
            pp  += __shfl_xor_sync(0xffffffffu, pp,  off);
            ppp += __shfl_xor_sync(0xffffffffu, ppp, off);
        }

        float contrib = -fmaf(pp, dB, ppp * halfdt);   // -(ps*dB + pss*dt/2)
        if (j == 0) contrib += pu + sb4[n];            // terminal value term
        acc += contrib;
    }

    if (lane == 0) g_partial[st * B2 + b] = acc;
}

__global__ void bsde_final(const float* __restrict__ ss, float* __restrict__ out)
{
    int b = blockIdx.x * blockDim.x + threadIdx.x;
    if (b >= B2) return;
    float u = 0.0f;
#pragma unroll
    for (int st = 0; st < STEP_TILES; st++) u += g_partial[st * B2 + b];
    out[b] = u;
    // u0 = sqrt(beta/(2pi)) * exp(-beta*s0^2/2) / out_dim,  beta = 1e6
    float s0 = ss[b * NP1];
    out[B2 + b] = 3.9894228040143274f * expf(-500000.0f * (s0 * s0));
}

extern "C" void kernel_launch(void* const* d_in, const int* in_sizes, int n_in,
                              void* d_out, int out_size)
{
    const float* W1   = (const float*)d_in[0];
    const float* b1   = (const float*)d_in[1];
    const float* W2   = (const float*)d_in[2];
    const float* b2   = (const float*)d_in[3];
    const float* W3   = (const float*)d_in[4];
    const float* b3   = (const float*)d_in[5];
    const float* W4   = (const float*)d_in[6];
    const float* b4   = (const float*)d_in[7];
    const int*   sn   = (const int*)d_in[8];
    const float* ss   = (const float*)d_in[9];
    const float* sdB  = (const float*)d_in[10];
    const float* tptr = (const float*)d_in[11];
    float* out = (float*)d_out;

    size_t smem_bytes = (size_t)(2 * HID * HID + OUTD * HID + 6 * HID + SPB * HID * 4) * sizeof(float);
    cudaFuncSetAttribute(bsde_main, cudaFuncAttributeMaxDynamicSharedMemorySize, (int)smem_bytes);

    bsde_main<<<NSB * STEP_TILES, THREADS, smem_bytes>>>(W1, b1, W2, b2, W3, b3, W4, b4,
                                                         sn, ss, sdB, tptr);
    bsde_final<<<(B2 + 255) / 256, 256>>>(ss, out);
}